// round 6
// baseline (speedup 1.0000x reference)
#include <cuda_runtime.h>
#include <cuda_fp16.h>
#include <cstdint>

#define D     256
#define S     2048
#define BATCH 8
#define M_TOTAL (BATCH * S)   // 16384
#define KC    (3 * D)         // 768
#define PART  32

#define MTILES (M_TOTAL / 128)    // 128
#define BCH    32768              // B chunk: 256 n x 64 k fp16 (swizzled)
#define ACH    16384              // A chunk: 128 m x 64 k fp16 (swizzled)

// SMEM layout (bytes, from dynamic smem base)
#define XROWS  132
#define XSTRIDE_F 68                       // floats per window row (padded)
#define XW_BYTES (XROWS * XSTRIDE_F * 4)   // 35904
#define A_BASE 36096                        // 128-aligned
#define B_BASE (A_BASE + 3 * ACH)           // 85248
#define GEMM_SMEM (B_BASE + 3 * BCH)        // 183552

// ---------------- scratch (static device globals) ----------------
__device__ float g_part[BATCH][PART][D];
__device__ float g_total[BATCH][D];
// B chunks stored PERMUTED to consumption order: slot p holds k-chunk c where
// p = 3*(c%4) + c/4   (consumption order 0,4,8,1,5,9,2,6,10,3,7,11)
__device__ __align__(16) unsigned char g_B[(size_t)12 * BCH];  // 384 KB

// ---------------- helpers ----------------
__device__ __forceinline__ uint32_t smem_u32(const void* p) {
    uint32_t a;
    asm("{ .reg .u64 t; cvta.to.shared.u64 t, %1; cvt.u32.u64 %0, t; }" : "=r"(a) : "l"(p));
    return a;
}
__device__ __forceinline__ uint32_t swoff(int row, int kk) {
    return (uint32_t)(row * 128 + ((((kk >> 3) ^ (row & 7)) << 4)) + (kk & 7) * 2);
}
__device__ __forceinline__ void cp16(uint32_t dst, const void* src) {
    asm volatile("cp.async.cg.shared.global [%0], [%1], 16;"
        :: "r"(dst), "l"(__cvta_generic_to_global(src)));
}
#define CP_COMMIT() asm volatile("cp.async.commit_group;")

__device__ __forceinline__ void ldm_x4(uint32_t addr, uint32_t* f) {
    asm volatile("ldmatrix.sync.aligned.m8n8.x4.shared.b16 {%0,%1,%2,%3}, [%4];"
        : "=r"(f[0]), "=r"(f[1]), "=r"(f[2]), "=r"(f[3]) : "r"(addr));
}
__device__ __forceinline__ uint32_t a_addr(uint32_t base, int r0, int k0, int lane) {
    int i = lane & 7, seg = lane >> 3;
    int row = r0 + i + ((seg & 1) << 3);
    int kk = k0 + ((seg >> 1) << 3);
    return base + (uint32_t)(row * 128) + ((((kk >> 3) ^ (row & 7)) << 4));
}
__device__ __forceinline__ uint32_t b_addr(uint32_t base, int n0, int k0, int lane) {
    int i = lane & 7, seg = lane >> 3;
    int row = n0 + i + ((seg >> 1) << 3);
    int kk = k0 + ((seg & 1) << 3);
    return base + (uint32_t)(row * 128) + ((((kk >> 3) ^ (row & 7)) << 4));
}
__device__ __forceinline__ void mma16816(float* c, const uint32_t* a, uint32_t b0, uint32_t b1) {
    asm volatile("mma.sync.aligned.m16n8k16.row.col.f32.f16.f16.f32 "
        "{%0,%1,%2,%3}, {%4,%5,%6,%7}, {%8,%9}, {%0,%1,%2,%3};"
        : "+f"(c[0]), "+f"(c[1]), "+f"(c[2]), "+f"(c[3])
        : "r"(a[0]), "r"(a[1]), "r"(a[2]), "r"(a[3]), "r"(b0), "r"(b1));
}
__device__ __forceinline__ uint2 pack_half4(const float* v) {
    __half2 lo = __floats2half2_rn(v[0], v[1]);
    __half2 hi = __floats2half2_rn(v[2], v[3]);
    uint2 u;
    u.x = *(const uint32_t*)&lo;
    u.y = *(const uint32_t*)&hi;
    return u;
}

// ---------------------------------------------------------------------------
// Kernel 1: column sums (two-stage, deterministic, float4)
// ---------------------------------------------------------------------------
__global__ void __launch_bounds__(128)
colsum_part(const float* __restrict__ x) {
    int b = blockIdx.x, p = blockIdx.y, tid = threadIdx.x;
    int c4 = (tid & 63) * 4;
    int rh = tid >> 6;
    const int chunk = S / PART;    // 64
    const int half = chunk / 2;    // 32
    const float* xp = x + ((long)b * S + (long)(p * chunk + rh * half)) * D + c4;
    float a0 = 0.f, a1 = 0.f, a2 = 0.f, a3 = 0.f;
    #pragma unroll 8
    for (int s = 0; s < half; ++s) {
        float4 v = *(const float4*)(xp + (long)s * D);
        a0 += v.x; a1 += v.y; a2 += v.z; a3 += v.w;
    }
    __shared__ float4 sh[64];
    if (rh == 1) sh[tid & 63] = make_float4(a0, a1, a2, a3);
    __syncthreads();
    if (rh == 0) {
        float4 o = sh[tid & 63];
        *(float4*)(&g_part[b][p][c4]) = make_float4(a0 + o.x, a1 + o.y, a2 + o.z, a3 + o.w);
    }
}
__global__ void __launch_bounds__(64)
colsum_reduce() {
    int b = blockIdx.x, c4 = threadIdx.x * 4;
    float a0 = 0.f, a1 = 0.f, a2 = 0.f, a3 = 0.f;
    #pragma unroll
    for (int p = 0; p < PART; ++p) {
        float4 v = *(const float4*)(&g_part[b][p][c4]);
        a0 += v.x; a1 += v.y; a2 += v.z; a3 += v.w;
    }
    *(float4*)(&g_total[b][c4]) = make_float4(a0, a1, a2, a3);
}

// ---------------------------------------------------------------------------
// Kernel 2: pack weights W[k][n] -> g_B[slot p][n 256][k 64], fp16, swizzled
// ---------------------------------------------------------------------------
__global__ void convert_w(const float* __restrict__ basis, const float* __restrict__ root) {
    int k = blockIdx.x;          // 0..767
    int n = threadIdx.x;         // 0..255
    float v = (k < 2 * D) ? basis[(size_t)k * D + n] : root[(size_t)(k - 2 * D) * D + n];
    int c = k >> 6, kk = k & 63;
    int p = 3 * (c & 3) + (c >> 2);      // permuted slot
    *(__half*)(g_B + (size_t)p * BCH + swoff(n, kk)) = __float2half_rn(v);
}

// ---------------------------------------------------------------------------
// Kernel 3: FUSED z-build + HMMA GEMM   out[16384,256] = z @ W + bias
// grid 128 (mtile), 512 threads, CTA tile 128x256.
// Per channel-group g (4 of them): x-window -> A chunks (z0,z1,x) in SMEM,
// then 3 MMA steps. cp.async static schedule (commits in fixed order; FIFO
// completion per thread makes the wait_group constants below exact).
// ---------------------------------------------------------------------------
__device__ __forceinline__ void issue_x(uint32_t xw, const float* xb, int t0, int g, int tid) {
    #pragma unroll
    for (int l = 0; l < 4; ++l) {
        int id = tid + l * 512;
        int w = id >> 4, q = id & 15;
        int tw = t0 - 1 + w;
        if (tw >= 0 && tw < S)
            cp16(xw + (uint32_t)(w * (XSTRIDE_F * 4) + q * 16),
                 xb + (size_t)tw * D + g * 64 + q * 4);
    }
    if (tid < 64) {
        int id = 2048 + tid;
        int w = id >> 4, q = id & 15;
        int tw = t0 - 1 + w;
        if (tw >= 0 && tw < S)
            cp16(xw + (uint32_t)(w * (XSTRIDE_F * 4) + q * 16),
                 xb + (size_t)tw * D + g * 64 + q * 4);
    }
}
__device__ __forceinline__ void issue_b(uint32_t sbase, int p, int tid) {
    uint32_t dst = sbase + B_BASE + (uint32_t)(p % 3) * BCH + (uint32_t)tid * 64;
    const unsigned char* src = g_B + (size_t)p * BCH + (size_t)tid * 64;
    #pragma unroll
    for (int l = 0; l < 4; ++l)
        cp16(dst + l * 16, src + l * 16);
}

__global__ void __launch_bounds__(512, 1)
gemm_fused(const float* __restrict__ x, const float* __restrict__ comp,
           const float* __restrict__ bias, float* __restrict__ out) {
    extern __shared__ unsigned char smem[];
    uint32_t sbase = smem_u32(smem);
    float* xs = (float*)smem;

    int tid = threadIdx.x, lane = tid & 31, wid = tid >> 5;
    int wm = wid >> 2, wn = wid & 3;      // 4x4 warp grid; warp tile 32x64
    int mtile = blockIdx.x;
    int b = mtile >> 4;
    int t0 = (mtile & 15) << 7;
    const float* xb = x + (size_t)b * S * D;

    // comp coefficients
    float c00 = comp[0], c10 = comp[2], c20 = comp[4], c30 = comp[6];
    float c01 = comp[1], c11 = comp[3], c21 = comp[5], c31 = comp[7];

    // per-thread z rows/channels for compute phase
    int zr = tid >> 2;                // 0..127
    int zcq = (tid & 3) * 16;         // channel base within group (0,16,32,48)
    int zt = t0 + zr;
    bool pm1 = (zt >= 1), pp1 = (zt + 1 < S), pp2 = (zt + 2 < S), pp3 = (zt + 3 < S);
    float inv1 = 1.f / (1.f + (float)pp2);
    int n2i = (int)pm1 + (int)pp3;
    float inv2 = n2i ? 1.f / (float)n2i : 0.f;
    float inv3 = 1.f / (float)(S - (1 + (int)pm1 + (int)pp1 + (int)pp2 + (int)pp3));

    // prologue commits: [x0][B0][B1]
    issue_x(sbase, xb, t0, 0, tid); CP_COMMIT();
    issue_b(sbase, 0, tid);         CP_COMMIT();
    issue_b(sbase, 1, tid);         CP_COMMIT();

    float acc[2][8][4];
    #pragma unroll
    for (int mt = 0; mt < 2; ++mt)
        #pragma unroll
        for (int nt = 0; nt < 8; ++nt)
            #pragma unroll
            for (int q = 0; q < 4; ++q) acc[mt][nt][q] = 0.f;

    #pragma unroll 1
    for (int g = 0; g < 4; ++g) {
        int s = 3 * g;
        // ---- step j=0: wait x_g + B_s (K=1), compute A, MMA ----
        asm volatile("cp.async.wait_group 1;");
        __syncthreads();

        // compute A chunks (z0 -> slot0, z1 -> slot1, x -> slot2)
        {
            float4 tot4 = *(const float4*)(&g_total[b][g * 64 + zcq]);
            float totv[4] = {tot4.x, tot4.y, tot4.z, tot4.w};
            #pragma unroll
            for (int c = 0; c < 4; ++c) {
                int ch = zcq + c * 4;
                const float* base = xs + ch;
                float4 zz = make_float4(0.f, 0.f, 0.f, 0.f);
                float4 tm1 = pm1 ? *(const float4*)(base + (zr + 0) * XSTRIDE_F) : zz;
                float4 t00 =       *(const float4*)(base + (zr + 1) * XSTRIDE_F);
                float4 tp1 = pp1 ? *(const float4*)(base + (zr + 2) * XSTRIDE_F) : zz;
                float4 tp2 = pp2 ? *(const float4*)(base + (zr + 3) * XSTRIDE_F) : zz;
                float4 tp3 = pp3 ? *(const float4*)(base + (zr + 4) * XSTRIDE_F) : zz;
                float xm1[4] = {tm1.x, tm1.y, tm1.z, tm1.w};
                float x00[4] = {t00.x, t00.y, t00.z, t00.w};
                float xp1[4] = {tp1.x, tp1.y, tp1.z, tp1.w};
                float xp2[4] = {tp2.x, tp2.y, tp2.z, tp2.w};
                float xp3[4] = {tp3.x, tp3.y, tp3.z, tp3.w};
                float z0[4], z1[4];
                #pragma unroll
                for (int j = 0; j < 4; ++j) {
                    float tt = totv[j];
                    // reuse totv slot trick not needed; plain math
                    float wsum = xm1[j] + x00[j] + xp1[j] + xp2[j] + xp3[j];
                    float a0 = xp1[j];
                    float a1 = (x00[j] + xp2[j]) * inv1;
                    float a2 = (xm1[j] + xp3[j]) * inv2;
                    float a3 = (tt - wsum) * inv3;
                    z0[j] = c00 * a0 + c10 * a1 + c20 * a2 + c30 * a3;
                    z1[j] = c01 * a0 + c11 * a1 + c21 * a2 + c31 * a3;
                }
                // re-read totv for next c? totv is per-c4 group: fix below
                uint32_t o = swoff(zr, ch);
                *(uint2*)(smem + A_BASE + 0 * ACH + o) = pack_half4(z0);
                *(uint2*)(smem + A_BASE + 1 * ACH + o) = pack_half4(z1);
                *(uint2*)(smem + A_BASE + 2 * ACH + o) = pack_half4(x00);
                if (c < 3) {
                    float4 nt4 = *(const float4*)(&g_total[b][g * 64 + zcq + (c + 1) * 4]);
                    totv[0] = nt4.x; totv[1] = nt4.y; totv[2] = nt4.z; totv[3] = nt4.w;
                }
            }
        }
        __syncthreads();

        // MMA step j=0 (A slot 0, B slot s%3)
        #pragma unroll 1
        for (int j = 0; j < 3; ++j, ++s) {
            if (j == 1) {
                if (s == 10) asm volatile("cp.async.wait_group 1;");
                else         asm volatile("cp.async.wait_group 2;");
                __syncthreads();
            } else if (j == 2) {
                if (s == 11) asm volatile("cp.async.wait_group 0;");
                else         asm volatile("cp.async.wait_group 2;");
                __syncthreads();
            }
            uint32_t Ab = sbase + A_BASE + (uint32_t)j * ACH;
            uint32_t Bb = sbase + B_BASE + (uint32_t)(s % 3) * BCH;
            #pragma unroll
            for (int k16 = 0; k16 < 4; ++k16) {
                int k0 = k16 * 16;
                uint32_t ah[2][4];
                #pragma unroll
                for (int mt = 0; mt < 2; ++mt)
                    ldm_x4(a_addr(Ab, wm * 32 + mt * 16, k0, lane), ah[mt]);
                #pragma unroll
                for (int gg = 0; gg < 4; ++gg) {
                    uint32_t bh[4];
                    ldm_x4(b_addr(Bb, wn * 64 + gg * 16, k0, lane), bh);
                    #pragma unroll
                    for (int mt = 0; mt < 2; ++mt) {
                        mma16816(acc[mt][2 * gg],     ah[mt], bh[0], bh[1]);
                        mma16816(acc[mt][2 * gg + 1], ah[mt], bh[2], bh[3]);
                    }
                }
            }
            // commits after MMA issue
            if (s + 2 < 12) { issue_b(sbase, s + 2, tid); CP_COMMIT(); }
            if (j == 0 && g < 3) { issue_x(sbase, xb, t0, g + 1, tid); CP_COMMIT(); }
        }
    }

    // epilogue: bias + store
    int rbase = mtile * 128 + wm * 32 + (lane >> 2);
    int cbase = wn * 64 + (lane & 3) * 2;
    #pragma unroll
    for (int mt = 0; mt < 2; ++mt) {
        #pragma unroll
        for (int nt = 0; nt < 8; ++nt) {
            int row = rbase + mt * 16;
            int col = cbase + nt * 8;
            float b0 = bias[col], b1 = bias[col + 1];
            float2 v;
            v.x = acc[mt][nt][0] + b0; v.y = acc[mt][nt][1] + b1;
            *(float2*)(out + (size_t)row * D + col) = v;
            v.x = acc[mt][nt][2] + b0; v.y = acc[mt][nt][3] + b1;
            *(float2*)(out + (size_t)(row + 8) * D + col) = v;
        }
    }
}

// ---------------------------------------------------------------------------
extern "C" void kernel_launch(void* const* d_in, const int* in_sizes, int n_in,
                              void* d_out, int out_size) {
    const float* x     = (const float*)d_in[0];
    const float* comp  = (const float*)d_in[1];
    const float* basis = (const float*)d_in[2];
    const float* root  = (const float*)d_in[3];
    const float* bias  = (const float*)d_in[4];
    float* out = (float*)d_out;

    cudaFuncSetAttribute(gemm_fused, cudaFuncAttributeMaxDynamicSharedMemorySize, GEMM_SMEM);

    convert_w<<<KC, D>>>(basis, root);
    colsum_part<<<dim3(BATCH, PART), 128>>>(x);
    colsum_reduce<<<BATCH, 64>>>();
    gemm_fused<<<MTILES, 512, GEMM_SMEM>>>(x, comp, bias, out);
}

// round 8
// speedup vs baseline: 1.0034x; 1.0034x over previous
#include <cuda_runtime.h>
#include <cuda_fp16.h>
#include <cstdint>

#define D     256
#define S     2048
#define BATCH 8
#define M_TOTAL (BATCH * S)   // 16384
#define KC    (3 * D)         // 768
#define PART  32

#define MTILES (M_TOTAL / 128)    // 128
#define BCH    32768              // B chunk: 256 n x 64 k fp16 (swizzled)
#define ACH    16384              // A chunk: 128 m x 64 k fp16 (swizzled)

// SMEM: [A buf0: 3 chunks][A buf1: 3 chunks][B ring: 3 chunks]
#define ABUF_BYTES (3 * ACH)                 // 49152
#define B_BASE     (2 * ABUF_BYTES)          // 98304
#define GEMM_SMEM  (B_BASE + 3 * BCH)        // 196608

// ---------------- scratch (static device globals) ----------------
__device__ float g_part[BATCH][PART][D];
__device__ float g_total[BATCH][D];
// B chunks stored PERMUTED to consumption order: k-chunk c lives at slot
// p = 3*(c%4) + c/4. Consumption order: 0,4,8, 1,5,9, 2,6,10, 3,7,11.
__device__ __align__(16) unsigned char g_B[(size_t)12 * BCH];  // 384 KB

// ---------------- helpers ----------------
__device__ __forceinline__ uint32_t smem_u32(const void* p) {
    uint32_t a;
    asm("{ .reg .u64 t; cvta.to.shared.u64 t, %1; cvt.u32.u64 %0, t; }" : "=r"(a) : "l"(p));
    return a;
}
__device__ __forceinline__ uint32_t swoff(int row, int kk) {
    return (uint32_t)(row * 128 + ((((kk >> 3) ^ (row & 7)) << 4)) + (kk & 7) * 2);
}
__device__ __forceinline__ void cp16(uint32_t dst, const void* src) {
    asm volatile("cp.async.cg.shared.global [%0], [%1], 16;"
        :: "r"(dst), "l"(__cvta_generic_to_global(src)));
}
#define CP_COMMIT() asm volatile("cp.async.commit_group;")

__device__ __forceinline__ void ldm_x4(uint32_t addr, uint32_t* f) {
    asm volatile("ldmatrix.sync.aligned.m8n8.x4.shared.b16 {%0,%1,%2,%3}, [%4];"
        : "=r"(f[0]), "=r"(f[1]), "=r"(f[2]), "=r"(f[3]) : "r"(addr));
}
__device__ __forceinline__ uint32_t a_addr(uint32_t base, int r0, int k0, int lane) {
    int i = lane & 7, seg = lane >> 3;
    int row = r0 + i + ((seg & 1) << 3);
    int kk = k0 + ((seg >> 1) << 3);
    return base + (uint32_t)(row * 128) + ((((kk >> 3) ^ (row & 7)) << 4));
}
__device__ __forceinline__ uint32_t b_addr(uint32_t base, int n0, int k0, int lane) {
    int i = lane & 7, seg = lane >> 3;
    int row = n0 + i + ((seg >> 1) << 3);
    int kk = k0 + ((seg & 1) << 3);
    return base + (uint32_t)(row * 128) + ((((kk >> 3) ^ (row & 7)) << 4));
}
__device__ __forceinline__ void mma16816(float* c, const uint32_t* a, uint32_t b0, uint32_t b1) {
    asm volatile("mma.sync.aligned.m16n8k16.row.col.f32.f16.f16.f32 "
        "{%0,%1,%2,%3}, {%4,%5,%6,%7}, {%8,%9}, {%0,%1,%2,%3};"
        : "+f"(c[0]), "+f"(c[1]), "+f"(c[2]), "+f"(c[3])
        : "r"(a[0]), "r"(a[1]), "r"(a[2]), "r"(a[3]), "r"(b0), "r"(b1));
}
__device__ __forceinline__ uint2 pack_half4(const float* v) {
    __half2 lo = __floats2half2_rn(v[0], v[1]);
    __half2 hi = __floats2half2_rn(v[2], v[3]);
    uint2 u;
    u.x = *(const uint32_t*)&lo;
    u.y = *(const uint32_t*)&hi;
    return u;
}

// ---------------------------------------------------------------------------
// Kernel 1: prep = colsum partials (blocks 0..255) + weight pack (blocks 256..1023)
// ---------------------------------------------------------------------------
__global__ void __launch_bounds__(128)
prep(const float* __restrict__ x, const float* __restrict__ basis,
     const float* __restrict__ root) {
    int blk = blockIdx.x, tid = threadIdx.x;
    if (blk < BATCH * PART) {
        int b = blk >> 5, p = blk & 31;
        int c4 = (tid & 63) * 4;
        int rh = tid >> 6;
        const int chunk = S / PART;    // 64
        const int half = chunk / 2;    // 32
        const float* xp = x + ((long)b * S + (long)(p * chunk + rh * half)) * D + c4;
        float a0 = 0.f, a1 = 0.f, a2 = 0.f, a3 = 0.f;
        #pragma unroll 8
        for (int s = 0; s < half; ++s) {
            float4 v = *(const float4*)(xp + (long)s * D);
            a0 += v.x; a1 += v.y; a2 += v.z; a3 += v.w;
        }
        __shared__ float4 sh[64];
        if (rh == 1) sh[tid & 63] = make_float4(a0, a1, a2, a3);
        __syncthreads();
        if (rh == 0) {
            float4 o = sh[tid & 63];
            *(float4*)(&g_part[b][p][c4]) =
                make_float4(a0 + o.x, a1 + o.y, a2 + o.z, a3 + o.w);
        }
    } else {
        int k = blk - BATCH * PART;    // 0..767
        int c = k >> 6, kk = k & 63;
        int p = 3 * (c & 3) + (c >> 2);
        unsigned char* blkp = g_B + (size_t)p * BCH;
        #pragma unroll
        for (int h = 0; h < 2; ++h) {
            int n = tid + h * 128;
            float v = (k < 2 * D) ? basis[(size_t)k * D + n]
                                  : root[(size_t)(k - 2 * D) * D + n];
            *(__half*)(blkp + swoff(n, kk)) = __float2half_rn(v);
        }
    }
}
__global__ void __launch_bounds__(64)
colsum_reduce() {
    int b = blockIdx.x, c4 = threadIdx.x * 4;
    float a0 = 0.f, a1 = 0.f, a2 = 0.f, a3 = 0.f;
    #pragma unroll
    for (int p = 0; p < PART; ++p) {
        float4 v = *(const float4*)(&g_part[b][p][c4]);
        a0 += v.x; a1 += v.y; a2 += v.z; a3 += v.w;
    }
    *(float4*)(&g_total[b][c4]) = make_float4(a0, a1, a2, a3);
}

// ---------------------------------------------------------------------------
// Kernel 2: FUSED z-build + HMMA GEMM   out[16384,256] = z @ W + bias
// grid 128, 512 threads, CTA tile 128x256. A double-buffered (z built from
// direct global x loads, overlapped with MMA); B via 3-slot cp.async ring,
// lookahead +2 (slot (s+2)%3: last readers were step s-1 and passed the
// step-s barrier before the issue — no slot aliasing with live readers).
// ---------------------------------------------------------------------------
__device__ __forceinline__ void issue_b(uint32_t sbase, int p, int tid) {
    uint32_t dst = sbase + B_BASE + (uint32_t)(p % 3) * BCH + (uint32_t)tid * 64;
    const unsigned char* src = g_B + (size_t)p * BCH + (size_t)tid * 64;
    #pragma unroll
    for (int l = 0; l < 4; ++l)
        cp16(dst + l * 16, src + l * 16);
}

struct ZCtx {
    const float* xb;
    const float* totb;
    int zr, zcq, zt;
    bool pm1, pp1, pp2, pp3;
    float inv1, inv2, inv3;
    float c00, c10, c20, c30, c01, c11, c21, c31;
};

__device__ __forceinline__ void compute_z(unsigned char* smem, uint32_t abuf_off,
                                          const ZCtx& Z, int g) {
    #pragma unroll
    for (int c = 0; c < 4; ++c) {
        int kk = Z.zcq + c * 4;
        int ch = g * 64 + kk;
        const float* p = Z.xb + (size_t)Z.zt * D + ch;
        float4 zz = make_float4(0.f, 0.f, 0.f, 0.f);
        float4 tm1 = Z.pm1 ? *(const float4*)(p - D)     : zz;
        float4 t00 =         *(const float4*)(p);
        float4 tp1 = Z.pp1 ? *(const float4*)(p + D)     : zz;
        float4 tp2 = Z.pp2 ? *(const float4*)(p + 2 * D) : zz;
        float4 tp3 = Z.pp3 ? *(const float4*)(p + 3 * D) : zz;
        float4 tt  = *(const float4*)(Z.totb + ch);
        float xm1[4] = {tm1.x, tm1.y, tm1.z, tm1.w};
        float x00[4] = {t00.x, t00.y, t00.z, t00.w};
        float xp1[4] = {tp1.x, tp1.y, tp1.z, tp1.w};
        float xp2[4] = {tp2.x, tp2.y, tp2.z, tp2.w};
        float xp3[4] = {tp3.x, tp3.y, tp3.z, tp3.w};
        float tot[4] = {tt.x, tt.y, tt.z, tt.w};
        float z0[4], z1[4];
        #pragma unroll
        for (int j = 0; j < 4; ++j) {
            float wsum = xm1[j] + x00[j] + xp1[j] + xp2[j] + xp3[j];
            float a0 = xp1[j];
            float a1 = (x00[j] + xp2[j]) * Z.inv1;
            float a2 = (xm1[j] + xp3[j]) * Z.inv2;
            float a3 = (tot[j] - wsum) * Z.inv3;
            z0[j] = Z.c00 * a0 + Z.c10 * a1 + Z.c20 * a2 + Z.c30 * a3;
            z1[j] = Z.c01 * a0 + Z.c11 * a1 + Z.c21 * a2 + Z.c31 * a3;
        }
        uint32_t o = abuf_off + swoff(Z.zr, kk);
        *(uint2*)(smem + o + 0 * ACH) = pack_half4(z0);
        *(uint2*)(smem + o + 1 * ACH) = pack_half4(z1);
        *(uint2*)(smem + o + 2 * ACH) = pack_half4(x00);
    }
}

__global__ void __launch_bounds__(512, 1)
gemm_fused(const float* __restrict__ x, const float* __restrict__ comp,
           const float* __restrict__ bias, float* __restrict__ out) {
    extern __shared__ unsigned char smem[];
    uint32_t sbase = smem_u32(smem);

    int tid = threadIdx.x, lane = tid & 31, wid = tid >> 5;
    int wm = wid >> 2, wn = wid & 3;      // 4x4 warp grid; warp tile 32x64
    int mtile = blockIdx.x;
    int b = mtile >> 4;
    int t0 = (mtile & 15) << 7;

    ZCtx Z;
    Z.xb = x + (size_t)b * S * D;
    Z.totb = &g_total[b][0];
    Z.zr = tid >> 2;
    Z.zcq = (tid & 3) * 16;
    Z.zt = t0 + Z.zr;
    Z.pm1 = (Z.zt >= 1); Z.pp1 = (Z.zt + 1 < S);
    Z.pp2 = (Z.zt + 2 < S); Z.pp3 = (Z.zt + 3 < S);
    Z.inv1 = 1.f / (1.f + (float)Z.pp2);
    int n2i = (int)Z.pm1 + (int)Z.pp3;
    Z.inv2 = n2i ? 1.f / (float)n2i : 0.f;
    Z.inv3 = 1.f / (float)(S - (1 + (int)Z.pm1 + (int)Z.pp1 + (int)Z.pp2 + (int)Z.pp3));
    Z.c00 = comp[0]; Z.c10 = comp[2]; Z.c20 = comp[4]; Z.c30 = comp[6];
    Z.c01 = comp[1]; Z.c11 = comp[3]; Z.c21 = comp[5]; Z.c31 = comp[7];

    // prologue: 2 B chunks in flight + z group 0 into buf 0
    issue_b(sbase, 0, tid); CP_COMMIT();
    issue_b(sbase, 1, tid); CP_COMMIT();
    compute_z(smem, 0, Z, 0);

    float acc[2][8][4];
    #pragma unroll
    for (int mt = 0; mt < 2; ++mt)
        #pragma unroll
        for (int nt = 0; nt < 8; ++nt)
            #pragma unroll
            for (int q = 0; q < 4; ++q) acc[mt][nt][q] = 0.f;

    #pragma unroll 1
    for (int g = 0; g < 4; ++g) {
        #pragma unroll 1
        for (int j = 0; j < 3; ++j) {
            int s = 3 * g + j;
            // pending groups here = {B_s, B_{s+1}} (B_{s+2} issued after this wait)
            if (s <= 10) asm volatile("cp.async.wait_group 1;");
            else         asm volatile("cp.async.wait_group 0;");
            __syncthreads();   // also publishes A buf writes for this group

            uint32_t Ab = sbase + (uint32_t)(g & 1) * ABUF_BYTES + (uint32_t)j * ACH;
            uint32_t Bb = sbase + B_BASE + (uint32_t)(s % 3) * BCH;
            #pragma unroll
            for (int k16 = 0; k16 < 4; ++k16) {
                int k0 = k16 * 16;
                uint32_t ah[2][4];
                #pragma unroll
                for (int mt = 0; mt < 2; ++mt)
                    ldm_x4(a_addr(Ab, wm * 32 + mt * 16, k0, lane), ah[mt]);
                #pragma unroll
                for (int gg = 0; gg < 4; ++gg) {
                    uint32_t bh[4];
                    ldm_x4(b_addr(Bb, wn * 64 + gg * 16, k0, lane), bh);
                    #pragma unroll
                    for (int mt = 0; mt < 2; ++mt) {
                        mma16816(acc[mt][2 * gg],     ah[mt], bh[0], bh[1]);
                        mma16816(acc[mt][2 * gg + 1], ah[mt], bh[2], bh[3]);
                    }
                }
            }
            if (s + 2 < 12) { issue_b(sbase, s + 2, tid); CP_COMMIT(); }
            if (j == 0 && g < 3)
                compute_z(smem, (uint32_t)((g + 1) & 1) * ABUF_BYTES, Z, g + 1);
        }
    }

    // epilogue: bias + store
    int rbase = mtile * 128 + wm * 32 + (lane >> 2);
    int cbase = wn * 64 + (lane & 3) * 2;
    #pragma unroll
    for (int mt = 0; mt < 2; ++mt) {
        #pragma unroll
        for (int nt = 0; nt < 8; ++nt) {
            int row = rbase + mt * 16;
            int col = cbase + nt * 8;
            float b0 = bias[col], b1 = bias[col + 1];
            float2 v;
            v.x = acc[mt][nt][0] + b0; v.y = acc[mt][nt][1] + b1;
            *(float2*)(out + (size_t)row * D + col) = v;
            v.x = acc[mt][nt][2] + b0; v.y = acc[mt][nt][3] + b1;
            *(float2*)(out + (size_t)(row + 8) * D + col) = v;
        }
    }
}

// ---------------------------------------------------------------------------
extern "C" void kernel_launch(void* const* d_in, const int* in_sizes, int n_in,
                              void* d_out, int out_size) {
    const float* x     = (const float*)d_in[0];
    const float* comp  = (const float*)d_in[1];
    const float* basis = (const float*)d_in[2];
    const float* root  = (const float*)d_in[3];
    const float* bias  = (const float*)d_in[4];
    float* out = (float*)d_out;

    cudaFuncSetAttribute(gemm_fused, cudaFuncAttributeMaxDynamicSharedMemorySize, GEMM_SMEM);

    prep<<<BATCH * PART + KC, 128>>>(x, basis, root);
    colsum_reduce<<<BATCH, 64>>>();
    gemm_fused<<<MTILES, 512, GEMM_SMEM>>>(x, comp, bias, out);
}

// round 9
// speedup vs baseline: 1.0928x; 1.0892x over previous
#include <cuda_runtime.h>
#include <cuda_fp16.h>
#include <cstdint>

#define D     256
#define S     2048
#define BATCH 8
#define M_TOTAL (BATCH * S)   // 16384
#define KC    (3 * D)         // 768
#define PART  64

#define NCHUNK 12                 // K chunks of 64
#define ACH    16384              // A chunk: 128x64 fp16 (swizzled)
#define BCH    32768              // B chunk: 256x64 fp16 (swizzled)
#define MTILES (M_TOTAL / 128)    // 128
#define STAGE_BYTES (ACH + BCH)   // 49152
#define NSTAGE 4
#define GEMM_SMEM (NSTAGE * STAGE_BYTES)  // 196608

// ---------------- scratch (static device globals) ----------------
__device__ float g_part[BATCH][PART][D];
__device__ float g_total[BATCH][D];
__device__ __align__(16) unsigned char g_A[(size_t)MTILES * NCHUNK * ACH];  // 24 MB
__device__ __align__(16) unsigned char g_B[(size_t)NCHUNK * BCH];           // 384 KB

// ---------------- helpers ----------------
__device__ __forceinline__ uint32_t smem_u32(const void* p) {
    uint32_t a;
    asm("{ .reg .u64 t; cvta.to.shared.u64 t, %1; cvt.u32.u64 %0, t; }" : "=r"(a) : "l"(p));
    return a;
}
__device__ __forceinline__ uint32_t swoff(int row, int kk) {
    return (uint32_t)(row * 128 + ((((kk >> 3) ^ (row & 7)) << 4)) + (kk & 7) * 2);
}
__device__ __forceinline__ void cp16(uint32_t dst, const void* src) {
    asm volatile("cp.async.cg.shared.global [%0], [%1], 16;"
        :: "r"(dst), "l"(__cvta_generic_to_global(src)));
}
__device__ __forceinline__ void ldm_x4(uint32_t addr, uint32_t* f) {
    asm volatile("ldmatrix.sync.aligned.m8n8.x4.shared.b16 {%0,%1,%2,%3}, [%4];"
        : "=r"(f[0]), "=r"(f[1]), "=r"(f[2]), "=r"(f[3]) : "r"(addr));
}
__device__ __forceinline__ uint32_t a_addr(uint32_t base, int r0, int k0, int lane) {
    int i = lane & 7, seg = lane >> 3;
    int row = r0 + i + ((seg & 1) << 3);
    int kk = k0 + ((seg >> 1) << 3);
    return base + (uint32_t)(row * 128) + ((((kk >> 3) ^ (row & 7)) << 4));
}
__device__ __forceinline__ uint32_t b_addr(uint32_t base, int n0, int k0, int lane) {
    int i = lane & 7, seg = lane >> 3;
    int row = n0 + i + ((seg >> 1) << 3);
    int kk = k0 + ((seg & 1) << 3);
    return base + (uint32_t)(row * 128) + ((((kk >> 3) ^ (row & 7)) << 4));
}
__device__ __forceinline__ void mma16816(float* c, const uint32_t* a, uint32_t b0, uint32_t b1) {
    asm volatile("mma.sync.aligned.m16n8k16.row.col.f32.f16.f16.f32 "
        "{%0,%1,%2,%3}, {%4,%5,%6,%7}, {%8,%9}, {%0,%1,%2,%3};"
        : "+f"(c[0]), "+f"(c[1]), "+f"(c[2]), "+f"(c[3])
        : "r"(a[0]), "r"(a[1]), "r"(a[2]), "r"(a[3]), "r"(b0), "r"(b1));
}
__device__ __forceinline__ uint2 pack_half4(const float* v) {
    __half2 lo = __floats2half2_rn(v[0], v[1]);
    __half2 hi = __floats2half2_rn(v[2], v[3]);
    uint2 u;
    u.x = *(const uint32_t*)&lo;
    u.y = *(const uint32_t*)&hi;
    return u;
}

// ---------------------------------------------------------------------------
// Kernel 1: column sums (two-stage, deterministic, float4, PART=64)
// ---------------------------------------------------------------------------
__global__ void __launch_bounds__(128)
colsum_part(const float* __restrict__ x) {
    int b = blockIdx.x, p = blockIdx.y, tid = threadIdx.x;
    int c4 = (tid & 63) * 4;
    int rh = tid >> 6;
    const int chunk = S / PART;    // 32
    const int half = chunk / 2;    // 16
    const float* xp = x + ((long)b * S + (long)(p * chunk + rh * half)) * D + c4;
    float a0 = 0.f, a1 = 0.f, a2 = 0.f, a3 = 0.f;
    #pragma unroll 8
    for (int s = 0; s < half; ++s) {
        float4 v = *(const float4*)(xp + (long)s * D);
        a0 += v.x; a1 += v.y; a2 += v.z; a3 += v.w;
    }
    __shared__ float4 sh[64];
    if (rh == 1) sh[tid & 63] = make_float4(a0, a1, a2, a3);
    __syncthreads();
    if (rh == 0) {
        float4 o = sh[tid & 63];
        *(float4*)(&g_part[b][p][c4]) = make_float4(a0 + o.x, a1 + o.y, a2 + o.z, a3 + o.w);
    }
}
__global__ void __launch_bounds__(64)
colsum_reduce() {
    int b = blockIdx.x, c4 = threadIdx.x * 4;
    float a0 = 0.f, a1 = 0.f, a2 = 0.f, a3 = 0.f;
    #pragma unroll
    for (int p = 0; p < PART; ++p) {
        float4 v = *(const float4*)(&g_part[b][p][c4]);
        a0 += v.x; a1 += v.y; a2 += v.z; a3 += v.w;
    }
    *(float4*)(&g_total[b][c4]) = make_float4(a0, a1, a2, a3);
}

// ---------------------------------------------------------------------------
// Kernel 2: build z = [z0 | z1 | x], fp16, rolling 5-tap window, 4 t-rows/thread
// grid (S/16, BATCH), 256 threads. Numerics identical to R5.
// ---------------------------------------------------------------------------
__global__ void __launch_bounds__(256)
build_z_pack(const float* __restrict__ x, const float* __restrict__ comp) {
    int b = blockIdx.y, tid = threadIdx.x;
    int t0 = blockIdx.x * 16;
    int i = (tid & 63) * 4;           // channel base
    int tbase = t0 + (tid >> 6) * 4;  // first of 4 t-rows for this thread
    const float* xb = x + (size_t)b * S * D;

    float c00 = comp[0], c10 = comp[2], c20 = comp[4], c30 = comp[6];
    float c01 = comp[1], c11 = comp[3], c21 = comp[5], c31 = comp[7];

    float4 tt4 = *(const float4*)(&g_total[b][i]);
    float tot[4] = {tt4.x, tt4.y, tt4.z, tt4.w};

    // rolling window: w[0..4] = rows tbase-1 .. tbase+3
    float4 w[5];
    #pragma unroll
    for (int j = 0; j < 5; ++j) {
        int row = tbase - 1 + j;
        w[j] = (row >= 0 && row < S) ? *(const float4*)(xb + (size_t)row * D + i)
                                     : make_float4(0.f, 0.f, 0.f, 0.f);
    }

    int mtile = (b * S + t0) >> 7;    // constant within block (16 <= 128 aligned)
    unsigned char* tb = g_A + (size_t)(mtile * NCHUNK) * ACH;
    int ch = i >> 6, kk = i & 63;

    #pragma unroll
    for (int it = 0; it < 4; ++it) {
        int t = tbase + it;
        bool pm1 = (t >= 1), pp1 = (t + 1 < S), pp2 = (t + 2 < S), pp3 = (t + 3 < S);
        float inv1 = 1.f / (1.f + (float)pp2);
        int n2i = (int)pm1 + (int)pp3;
        float inv2 = n2i ? 1.f / (float)n2i : 0.f;
        float inv3 = 1.f / (float)(S - (1 + (int)pm1 + (int)pp1 + (int)pp2 + (int)pp3));

        float xm1[4] = {w[0].x, w[0].y, w[0].z, w[0].w};
        float x00[4] = {w[1].x, w[1].y, w[1].z, w[1].w};
        float xp1[4] = {w[2].x, w[2].y, w[2].z, w[2].w};
        float xp2[4] = {w[3].x, w[3].y, w[3].z, w[3].w};
        float xp3[4] = {w[4].x, w[4].y, w[4].z, w[4].w};
        float z0[4], z1[4];
        #pragma unroll
        for (int j = 0; j < 4; ++j) {
            float wsum = xm1[j] + x00[j] + xp1[j] + xp2[j] + xp3[j];
            float a0 = xp1[j];
            float a1 = (x00[j] + xp2[j]) * inv1;
            float a2 = (xm1[j] + xp3[j]) * inv2;
            float a3 = (tot[j] - wsum) * inv3;
            z0[j] = c00 * a0 + c10 * a1 + c20 * a2 + c30 * a3;
            z1[j] = c01 * a0 + c11 * a1 + c21 * a2 + c31 * a3;
        }

        int r = (b * S + t) & 127;
        uint32_t o = swoff(r, kk);
        *(uint2*)(tb + (size_t)ch * ACH + o)       = pack_half4(z0);
        *(uint2*)(tb + (size_t)(ch + 4) * ACH + o) = pack_half4(z1);
        *(uint2*)(tb + (size_t)(ch + 8) * ACH + o) = pack_half4(x00);

        if (it < 3) {
            w[0] = w[1]; w[1] = w[2]; w[2] = w[3]; w[3] = w[4];
            int row = t + 4;
            w[4] = (row < S) ? *(const float4*)(xb + (size_t)row * D + i)
                             : make_float4(0.f, 0.f, 0.f, 0.f);
        }
    }
}

// ---------------------------------------------------------------------------
// Kernel 3: pack weights W[k][n] -> g_B[chunk][n 256][k 64], fp16, swizzled
// ---------------------------------------------------------------------------
__global__ void convert_w(const float* __restrict__ basis, const float* __restrict__ root) {
    int k = blockIdx.x;          // 0..767
    int n = threadIdx.x;         // 0..255
    float v = (k < 2 * D) ? basis[(size_t)k * D + n] : root[(size_t)(k - 2 * D) * D + n];
    int chunk = k >> 6, kk = k & 63;
    *(__half*)(g_B + (size_t)chunk * BCH + swoff(n, kk)) = __float2half_rn(v);
}

// ---------------------------------------------------------------------------
// Kernel 4: HMMA GEMM  out[16384,256] = z @ W + bias  (1 pass, 4 stages)
// grid 128 (mtile), 512 threads, CTA tile 128x256, warp tile 32x64, BK=64
// ---------------------------------------------------------------------------
__device__ __forceinline__ void load_stage(uint32_t s, const unsigned char* A,
                                           const unsigned char* B, int tid) {
    uint32_t off = (uint32_t)tid * 16;
    cp16(s + off, A + off);
    cp16(s + 8192 + off, A + 8192 + off);
    #pragma unroll
    for (int i = 0; i < 4; ++i)
        cp16(s + ACH + off + (uint32_t)i * 8192, B + off + (uint32_t)i * 8192);
}

__global__ void __launch_bounds__(512, 1)
gemm_hmma(const float* __restrict__ bias, float* __restrict__ out) {
    extern __shared__ unsigned char smem[];
    uint32_t sbase = smem_u32(smem);
    int tid = threadIdx.x, lane = tid & 31, wid = tid >> 5;
    int wm = wid >> 2, wn = wid & 3;      // 4x4 warp grid; warp tile 32 x 64
    int mtile = blockIdx.x;

    const unsigned char* Asrc = g_A + (size_t)(mtile * NCHUNK) * ACH;

    #pragma unroll
    for (int s = 0; s < NSTAGE - 1; ++s) {
        load_stage(sbase + (uint32_t)s * STAGE_BYTES,
                   Asrc + (size_t)s * ACH, g_B + (size_t)s * BCH, tid);
        asm volatile("cp.async.commit_group;");
    }

    float acc[2][8][4];
    #pragma unroll
    for (int mt = 0; mt < 2; ++mt)
        #pragma unroll
        for (int nt = 0; nt < 8; ++nt)
            #pragma unroll
            for (int q = 0; q < 4; ++q) acc[mt][nt][q] = 0.f;

    for (int c = 0; c < NCHUNK; ++c) {
        if (c + NSTAGE - 1 < NCHUNK) {
            int cn = c + NSTAGE - 1;
            load_stage(sbase + (uint32_t)(cn & (NSTAGE - 1)) * STAGE_BYTES,
                       Asrc + (size_t)cn * ACH, g_B + (size_t)cn * BCH, tid);
            asm volatile("cp.async.commit_group;");
        }
        if (c <= NCHUNK - NSTAGE)      asm volatile("cp.async.wait_group 3;");
        else if (c == NCHUNK - 3)      asm volatile("cp.async.wait_group 2;");
        else if (c == NCHUNK - 2)      asm volatile("cp.async.wait_group 1;");
        else                           asm volatile("cp.async.wait_group 0;");
        __syncthreads();

        uint32_t st = sbase + (uint32_t)(c & (NSTAGE - 1)) * STAGE_BYTES;
        uint32_t Ah = st, Bh = st + ACH;

        #pragma unroll
        for (int k16 = 0; k16 < 4; ++k16) {
            int k0 = k16 * 16;
            uint32_t ah[2][4];
            #pragma unroll
            for (int mt = 0; mt < 2; ++mt)
                ldm_x4(a_addr(Ah, wm * 32 + mt * 16, k0, lane), ah[mt]);
            #pragma unroll
            for (int g = 0; g < 4; ++g) {
                uint32_t bh[4];
                ldm_x4(b_addr(Bh, wn * 64 + g * 16, k0, lane), bh);
                #pragma unroll
                for (int mt = 0; mt < 2; ++mt) {
                    mma16816(acc[mt][2 * g],     ah[mt], bh[0], bh[1]);
                    mma16816(acc[mt][2 * g + 1], ah[mt], bh[2], bh[3]);
                }
            }
        }
        __syncthreads();
    }

    // epilogue: bias + store
    int rbase = mtile * 128 + wm * 32 + (lane >> 2);
    int cbase = wn * 64 + (lane & 3) * 2;
    #pragma unroll
    for (int mt = 0; mt < 2; ++mt) {
        #pragma unroll
        for (int nt = 0; nt < 8; ++nt) {
            int row = rbase + mt * 16;
            int col = cbase + nt * 8;
            float b0 = bias[col], b1 = bias[col + 1];
            float2 v;
            v.x = acc[mt][nt][0] + b0; v.y = acc[mt][nt][1] + b1;
            *(float2*)(out + (size_t)row * D + col) = v;
            v.x = acc[mt][nt][2] + b0; v.y = acc[mt][nt][3] + b1;
            *(float2*)(out + (size_t)(row + 8) * D + col) = v;
        }
    }
}

// ---------------------------------------------------------------------------
extern "C" void kernel_launch(void* const* d_in, const int* in_sizes, int n_in,
                              void* d_out, int out_size) {
    const float* x     = (const float*)d_in[0];
    const float* comp  = (const float*)d_in[1];
    const float* basis = (const float*)d_in[2];
    const float* root  = (const float*)d_in[3];
    const float* bias  = (const float*)d_in[4];
    float* out = (float*)d_out;

    cudaFuncSetAttribute(gemm_hmma, cudaFuncAttributeMaxDynamicSharedMemorySize, GEMM_SMEM);

    convert_w<<<KC, D>>>(basis, root);
    colsum_part<<<dim3(BATCH, PART), 128>>>(x);
    colsum_reduce<<<BATCH, 64>>>();
    build_z_pack<<<dim3(S / 16, BATCH), 256>>>(x, comp);
    gemm_hmma<<<MTILES, 512, GEMM_SMEM>>>(bias, out);
}

// round 10
// speedup vs baseline: 1.1438x; 1.0467x over previous
#include <cuda_runtime.h>
#include <cuda_fp16.h>
#include <cstdint>

#define D     256
#define S     2048
#define BATCH 8
#define M_TOTAL (BATCH * S)   // 16384
#define KC    (3 * D)         // 768
#define PART  64

#define NCHUNK 12                 // K chunks of 64
#define ACH    16384              // A chunk: 128x64 fp16 (swizzled)
#define BCH    32768              // B chunk: 256x64 fp16 (swizzled)
#define MTILES (M_TOTAL / 128)    // 128
#define STAGE_BYTES (ACH + BCH)   // 49152
#define NSTAGE 4
#define GEMM_SMEM (NSTAGE * STAGE_BYTES)  // 196608

// ---------------- scratch (static device globals) ----------------
__device__ float g_part[BATCH][PART][D];
__device__ float g_total[BATCH][D];
__device__ __align__(16) unsigned char g_A[(size_t)MTILES * NCHUNK * ACH];  // 24 MB
__device__ __align__(16) unsigned char g_B[(size_t)NCHUNK * BCH];           // 384 KB

// ---------------- helpers ----------------
__device__ __forceinline__ uint32_t smem_u32(const void* p) {
    uint32_t a;
    asm("{ .reg .u64 t; cvta.to.shared.u64 t, %1; cvt.u32.u64 %0, t; }" : "=r"(a) : "l"(p));
    return a;
}
__device__ __forceinline__ uint32_t swoff(int row, int kk) {
    return (uint32_t)(row * 128 + ((((kk >> 3) ^ (row & 7)) << 4)) + (kk & 7) * 2);
}
__device__ __forceinline__ void cp16(uint32_t dst, const void* src) {
    asm volatile("cp.async.cg.shared.global [%0], [%1], 16;"
        :: "r"(dst), "l"(__cvta_generic_to_global(src)));
}
__device__ __forceinline__ void ldm_x4(uint32_t addr, uint32_t* f) {
    asm volatile("ldmatrix.sync.aligned.m8n8.x4.shared.b16 {%0,%1,%2,%3}, [%4];"
        : "=r"(f[0]), "=r"(f[1]), "=r"(f[2]), "=r"(f[3]) : "r"(addr));
}
__device__ __forceinline__ uint32_t a_addr(uint32_t base, int r0, int k0, int lane) {
    int i = lane & 7, seg = lane >> 3;
    int row = r0 + i + ((seg & 1) << 3);
    int kk = k0 + ((seg >> 1) << 3);
    return base + (uint32_t)(row * 128) + ((((kk >> 3) ^ (row & 7)) << 4));
}
__device__ __forceinline__ uint32_t b_addr(uint32_t base, int n0, int k0, int lane) {
    int i = lane & 7, seg = lane >> 3;
    int row = n0 + i + ((seg >> 1) << 3);
    int kk = k0 + ((seg & 1) << 3);
    return base + (uint32_t)(row * 128) + ((((kk >> 3) ^ (row & 7)) << 4));
}
__device__ __forceinline__ void mma16816(float* c, const uint32_t* a, uint32_t b0, uint32_t b1) {
    asm volatile("mma.sync.aligned.m16n8k16.row.col.f32.f16.f16.f32 "
        "{%0,%1,%2,%3}, {%4,%5,%6,%7}, {%8,%9}, {%0,%1,%2,%3};"
        : "+f"(c[0]), "+f"(c[1]), "+f"(c[2]), "+f"(c[3])
        : "r"(a[0]), "r"(a[1]), "r"(a[2]), "r"(a[3]), "r"(b0), "r"(b1));
}
__device__ __forceinline__ uint2 pack_half4(const float* v) {
    __half2 lo = __floats2half2_rn(v[0], v[1]);
    __half2 hi = __floats2half2_rn(v[2], v[3]);
    uint2 u;
    u.x = *(const uint32_t*)&lo;
    u.y = *(const uint32_t*)&hi;
    return u;
}

// ---------------------------------------------------------------------------
// Kernel 1: column sums (two-stage, deterministic, float4, PART=64)
// ---------------------------------------------------------------------------
__global__ void __launch_bounds__(128)
colsum_part(const float* __restrict__ x) {
    int b = blockIdx.x, p = blockIdx.y, tid = threadIdx.x;
    int c4 = (tid & 63) * 4;
    int rh = tid >> 6;
    const int chunk = S / PART;    // 32
    const int half = chunk / 2;    // 16
    const float* xp = x + ((long)b * S + (long)(p * chunk + rh * half)) * D + c4;
    float a0 = 0.f, a1 = 0.f, a2 = 0.f, a3 = 0.f;
    #pragma unroll 8
    for (int s = 0; s < half; ++s) {
        float4 v = *(const float4*)(xp + (long)s * D);
        a0 += v.x; a1 += v.y; a2 += v.z; a3 += v.w;
    }
    __shared__ float4 sh[64];
    if (rh == 1) sh[tid & 63] = make_float4(a0, a1, a2, a3);
    __syncthreads();
    if (rh == 0) {
        float4 o = sh[tid & 63];
        *(float4*)(&g_part[b][p][c4]) = make_float4(a0 + o.x, a1 + o.y, a2 + o.z, a3 + o.w);
    }
}
__global__ void __launch_bounds__(64)
colsum_reduce() {
    int b = blockIdx.x, c4 = threadIdx.x * 4;
    float a0 = 0.f, a1 = 0.f, a2 = 0.f, a3 = 0.f;
    #pragma unroll
    for (int p = 0; p < PART; ++p) {
        float4 v = *(const float4*)(&g_part[b][p][c4]);
        a0 += v.x; a1 += v.y; a2 += v.z; a3 += v.w;
    }
    *(float4*)(&g_total[b][c4]) = make_float4(a0, a1, a2, a3);
}

// ---------------------------------------------------------------------------
// Kernel 2: build z = [z0 | z1 | x], fp16, rolling 5-tap window, 4 t-rows/thread
// Interior fast path (t in [1, S-7]): no masks, no divides (constant inv).
// grid (S/16, BATCH), 256 threads. Numerics bit-identical to R5/R9.
// ---------------------------------------------------------------------------
__global__ void __launch_bounds__(256)
build_z_pack(const float* __restrict__ x, const float* __restrict__ comp) {
    int b = blockIdx.y, tid = threadIdx.x;
    int t0 = blockIdx.x * 16;
    int i = (tid & 63) * 4;           // channel base
    int tbase = t0 + (tid >> 6) * 4;  // first of 4 t-rows for this thread
    const float* xb = x + (size_t)b * S * D;

    float c00 = comp[0], c10 = comp[2], c20 = comp[4], c30 = comp[6];
    float c01 = comp[1], c11 = comp[3], c21 = comp[5], c31 = comp[7];

    float4 tt4 = *(const float4*)(&g_total[b][i]);
    float tot[4] = {tt4.x, tt4.y, tt4.z, tt4.w};

    int mtile = (b * S + t0) >> 7;
    unsigned char* tb = g_A + (size_t)(mtile * NCHUNK) * ACH;
    int ch = i >> 6, kk = i & 63;

    if (tbase >= 1 && tbase <= S - 7) {
        // ---------- interior fast path ----------
        const float inv1 = 0.5f;                    // == 1/(1+1) exactly
        const float inv2 = 0.5f;                    // == 1/2 exactly
        const float inv3 = 1.0f / (float)(S - 5);   // same rounding as fdiv

        float4 w[5];
        #pragma unroll
        for (int j = 0; j < 5; ++j)
            w[j] = *(const float4*)(xb + (size_t)(tbase - 1 + j) * D + i);

        #pragma unroll
        for (int it = 0; it < 4; ++it) {
            int t = tbase + it;
            float xm1[4] = {w[0].x, w[0].y, w[0].z, w[0].w};
            float x00[4] = {w[1].x, w[1].y, w[1].z, w[1].w};
            float xp1[4] = {w[2].x, w[2].y, w[2].z, w[2].w};
            float xp2[4] = {w[3].x, w[3].y, w[3].z, w[3].w};
            float xp3[4] = {w[4].x, w[4].y, w[4].z, w[4].w};
            float z0[4], z1[4];
            #pragma unroll
            for (int j = 0; j < 4; ++j) {
                float wsum = xm1[j] + x00[j] + xp1[j] + xp2[j] + xp3[j];
                float a0 = xp1[j];
                float a1 = (x00[j] + xp2[j]) * inv1;
                float a2 = (xm1[j] + xp3[j]) * inv2;
                float a3 = (tot[j] - wsum) * inv3;
                z0[j] = c00 * a0 + c10 * a1 + c20 * a2 + c30 * a3;
                z1[j] = c01 * a0 + c11 * a1 + c21 * a2 + c31 * a3;
            }
            int r = (b * S + t) & 127;
            uint32_t o = swoff(r, kk);
            *(uint2*)(tb + (size_t)ch * ACH + o)       = pack_half4(z0);
            *(uint2*)(tb + (size_t)(ch + 4) * ACH + o) = pack_half4(z1);
            *(uint2*)(tb + (size_t)(ch + 8) * ACH + o) = pack_half4(x00);
            if (it < 3) {
                w[0] = w[1]; w[1] = w[2]; w[2] = w[3]; w[3] = w[4];
                w[4] = *(const float4*)(xb + (size_t)(t + 4) * D + i);
            }
        }
    } else {
        // ---------- boundary slow path (tbase == 0 or tbase == S-4) ----------
        float4 w[5];
        #pragma unroll
        for (int j = 0; j < 5; ++j) {
            int row = tbase - 1 + j;
            w[j] = (row >= 0 && row < S) ? *(const float4*)(xb + (size_t)row * D + i)
                                         : make_float4(0.f, 0.f, 0.f, 0.f);
        }
        #pragma unroll
        for (int it = 0; it < 4; ++it) {
            int t = tbase + it;
            bool pm1 = (t >= 1), pp1 = (t + 1 < S), pp2 = (t + 2 < S), pp3 = (t + 3 < S);
            float inv1 = 1.f / (1.f + (float)pp2);
            int n2i = (int)pm1 + (int)pp3;
            float inv2 = n2i ? 1.f / (float)n2i : 0.f;
            float inv3 = 1.f / (float)(S - (1 + (int)pm1 + (int)pp1 + (int)pp2 + (int)pp3));

            float xm1[4] = {w[0].x, w[0].y, w[0].z, w[0].w};
            float x00[4] = {w[1].x, w[1].y, w[1].z, w[1].w};
            float xp1[4] = {w[2].x, w[2].y, w[2].z, w[2].w};
            float xp2[4] = {w[3].x, w[3].y, w[3].z, w[3].w};
            float xp3[4] = {w[4].x, w[4].y, w[4].z, w[4].w};
            float z0[4], z1[4];
            #pragma unroll
            for (int j = 0; j < 4; ++j) {
                float wsum = xm1[j] + x00[j] + xp1[j] + xp2[j] + xp3[j];
                float a0 = xp1[j];
                float a1 = (x00[j] + xp2[j]) * inv1;
                float a2 = (xm1[j] + xp3[j]) * inv2;
                float a3 = (tot[j] - wsum) * inv3;
                z0[j] = c00 * a0 + c10 * a1 + c20 * a2 + c30 * a3;
                z1[j] = c01 * a0 + c11 * a1 + c21 * a2 + c31 * a3;
            }
            int r = (b * S + t) & 127;
            uint32_t o = swoff(r, kk);
            *(uint2*)(tb + (size_t)ch * ACH + o)       = pack_half4(z0);
            *(uint2*)(tb + (size_t)(ch + 4) * ACH + o) = pack_half4(z1);
            *(uint2*)(tb + (size_t)(ch + 8) * ACH + o) = pack_half4(x00);
            if (it < 3) {
                w[0] = w[1]; w[1] = w[2]; w[2] = w[3]; w[3] = w[4];
                int row = t + 4;
                w[4] = (row < S) ? *(const float4*)(xb + (size_t)row * D + i)
                                 : make_float4(0.f, 0.f, 0.f, 0.f);
            }
        }
    }
}

// ---------------------------------------------------------------------------
// Kernel 3: pack weights W[k][n] -> g_B[chunk][n 256][k 64], fp16, swizzled
// ---------------------------------------------------------------------------
__global__ void convert_w(const float* __restrict__ basis, const float* __restrict__ root) {
    int k = blockIdx.x;          // 0..767
    int n = threadIdx.x;         // 0..255
    float v = (k < 2 * D) ? basis[(size_t)k * D + n] : root[(size_t)(k - 2 * D) * D + n];
    int chunk = k >> 6, kk = k & 63;
    *(__half*)(g_B + (size_t)chunk * BCH + swoff(n, kk)) = __float2half_rn(v);
}

// ---------------------------------------------------------------------------
// Kernel 4: HMMA GEMM  out[16384,256] = z @ W + bias  (1 pass, 4 stages)
// grid 128 (mtile), 512 threads, CTA tile 128x256, warp tile 32x64, BK=64
// ---------------------------------------------------------------------------
__device__ __forceinline__ void load_stage(uint32_t s, const unsigned char* A,
                                           const unsigned char* B, int tid) {
    uint32_t off = (uint32_t)tid * 16;
    cp16(s + off, A + off);
    cp16(s + 8192 + off, A + 8192 + off);
    #pragma unroll
    for (int i = 0; i < 4; ++i)
        cp16(s + ACH + off + (uint32_t)i * 8192, B + off + (uint32_t)i * 8192);
}

__global__ void __launch_bounds__(512, 1)
gemm_hmma(const float* __restrict__ bias, float* __restrict__ out) {
    extern __shared__ unsigned char smem[];
    uint32_t sbase = smem_u32(smem);
    int tid = threadIdx.x, lane = tid & 31, wid = tid >> 5;
    int wm = wid >> 2, wn = wid & 3;      // 4x4 warp grid; warp tile 32 x 64
    int mtile = blockIdx.x;

    const unsigned char* Asrc = g_A + (size_t)(mtile * NCHUNK) * ACH;

    #pragma unroll
    for (int s = 0; s < NSTAGE - 1; ++s) {
        load_stage(sbase + (uint32_t)s * STAGE_BYTES,
                   Asrc + (size_t)s * ACH, g_B + (size_t)s * BCH, tid);
        asm volatile("cp.async.commit_group;");
    }

    float acc[2][8][4];
    #pragma unroll
    for (int mt = 0; mt < 2; ++mt)
        #pragma unroll
        for (int nt = 0; nt < 8; ++nt)
            #pragma unroll
            for (int q = 0; q < 4; ++q) acc[mt][nt][q] = 0.f;

    for (int c = 0; c < NCHUNK; ++c) {
        if (c + NSTAGE - 1 < NCHUNK) {
            int cn = c + NSTAGE - 1;
            load_stage(sbase + (uint32_t)(cn & (NSTAGE - 1)) * STAGE_BYTES,
                       Asrc + (size_t)cn * ACH, g_B + (size_t)cn * BCH, tid);
            asm volatile("cp.async.commit_group;");
        }
        if (c <= NCHUNK - NSTAGE)      asm volatile("cp.async.wait_group 3;");
        else if (c == NCHUNK - 3)      asm volatile("cp.async.wait_group 2;");
        else if (c == NCHUNK - 2)      asm volatile("cp.async.wait_group 1;");
        else                           asm volatile("cp.async.wait_group 0;");
        __syncthreads();

        uint32_t st = sbase + (uint32_t)(c & (NSTAGE - 1)) * STAGE_BYTES;
        uint32_t Ah = st, Bh = st + ACH;

        #pragma unroll
        for (int k16 = 0; k16 < 4; ++k16) {
            int k0 = k16 * 16;
            uint32_t ah[2][4];
            #pragma unroll
            for (int mt = 0; mt < 2; ++mt)
                ldm_x4(a_addr(Ah, wm * 32 + mt * 16, k0, lane), ah[mt]);
            #pragma unroll
            for (int g = 0; g < 4; ++g) {
                uint32_t bh[4];
                ldm_x4(b_addr(Bh, wn * 64 + g * 16, k0, lane), bh);
                #pragma unroll
                for (int mt = 0; mt < 2; ++mt) {
                    mma16816(acc[mt][2 * g],     ah[mt], bh[0], bh[1]);
                    mma16816(acc[mt][2 * g + 1], ah[mt], bh[2], bh[3]);
                }
            }
        }
        __syncthreads();
    }

    // epilogue: bias + store
    int rbase = mtile * 128 + wm * 32 + (lane >> 2);
    int cbase = wn * 64 + (lane & 3) * 2;
    #pragma unroll
    for (int mt = 0; mt < 2; ++mt) {
        #pragma unroll
        for (int nt = 0; nt < 8; ++nt) {
            int row = rbase + mt * 16;
            int col = cbase + nt * 8;
            float b0 = bias[col], b1 = bias[col + 1];
            float2 v;
            v.x = acc[mt][nt][0] + b0; v.y = acc[mt][nt][1] + b1;
            *(float2*)(out + (size_t)row * D + col) = v;
            v.x = acc[mt][nt][2] + b0; v.y = acc[mt][nt][3] + b1;
            *(float2*)(out + (size_t)(row + 8) * D + col) = v;
        }
    }
}

// ---------------------------------------------------------------------------
extern "C" void kernel_launch(void* const* d_in, const int* in_sizes, int n_in,
                              void* d_out, int out_size) {
    const float* x     = (const float*)d_in[0];
    const float* comp  = (const float*)d_in[1];
    const float* basis = (const float*)d_in[2];
    const float* root  = (const float*)d_in[3];
    const float* bias  = (const float*)d_in[4];
    float* out = (float*)d_out;

    cudaFuncSetAttribute(gemm_hmma, cudaFuncAttributeMaxDynamicSharedMemorySize, GEMM_SMEM);

    convert_w<<<KC, D>>>(basis, root);
    colsum_part<<<dim3(BATCH, PART), 128>>>(x);
    colsum_reduce<<<BATCH, 64>>>();
    build_z_pack<<<dim3(S / 16, BATCH), 256>>>(x, comp);
    gemm_hmma<<<MTILES, 512, GEMM_SMEM>>>(bias, out);
}